// round 1
// baseline (speedup 1.0000x reference)
#include <cuda_runtime.h>
#include <math.h>

#define F   256
#define NG  1024

// ---------------- scratch (no allocation allowed) ----------------
__device__ float g_wf[NG * F];          // softmax-weighted feature mean per graph
__device__ int   g_cnt[NG];             // node count per graph
__device__ int   g_bound[NG + 1];       // segment boundaries
__device__ float g_x[NG * F];           // elu(proj(wf))
__device__ float g_gi[NG * 3 * F];      // x @ w_ih.T + b_ih
__device__ float g_gh[NG * 3 * F];      // h @ w_hh.T + b_hh

// ---------------- segment boundary scan (segment_ids sorted) ----------------
__global__ void boundary_kernel(const int* __restrict__ seg, int n) {
    int i = blockIdx.x * blockDim.x + threadIdx.x;
    if (i >= n) return;
    int s = seg[i];
    if (i == 0) {
        for (int g = 0; g <= s; ++g) g_bound[g] = 0;
    } else {
        int p = seg[i - 1];
        for (int g = p + 1; g <= s; ++g) g_bound[g] = i;
    }
    if (i == n - 1) {
        for (int g = s + 1; g <= NG; ++g) g_bound[g] = n;
    }
}

// ---------------- pooling: one block per graph, online softmax ----------------
// wf[g] = sum_n softmax(z_n) * node_feats[n],   z_n = leaky_relu(c_g + nf_n . lw2 + b)
__global__ void __launch_bounds__(256) pool_kernel(
    const float* __restrict__ nf, const float* __restrict__ gf,
    const float* __restrict__ lw, const float* __restrict__ lb)
{
    const int g    = blockIdx.x;
    const int tid  = threadIdx.x;
    const int warp = tid >> 5;
    const int lane = tid & 31;

    __shared__ float s_red[8];
    __shared__ float s_c;
    __shared__ float s_m[8], s_s[8];
    __shared__ float s_acc[8][F];

    // c_g = relu(g_feats[g]) . lw[0:256] + b
    {
        float v = fmaxf(gf[g * F + tid], 0.f) * lw[tid];
        #pragma unroll
        for (int o = 16; o; o >>= 1) v += __shfl_xor_sync(0xffffffffu, v, o);
        if (lane == 0) s_red[warp] = v;
    }
    __syncthreads();
    if (tid == 0) {
        float c = lb[0];
        #pragma unroll
        for (int w = 0; w < 8; ++w) c += s_red[w];
        s_c = c;
    }
    __syncthreads();
    const float c     = s_c;
    const int   start = g_bound[g];
    const int   end   = g_bound[g + 1];

    // per-lane chunk of logit_w node half: dims lane*8 .. lane*8+7
    float lw2[8];
    {
        const float4* p = reinterpret_cast<const float4*>(lw + F) + lane * 2;
        float4 a = p[0], b = p[1];
        lw2[0] = a.x; lw2[1] = a.y; lw2[2] = a.z; lw2[3] = a.w;
        lw2[4] = b.x; lw2[5] = b.y; lw2[6] = b.z; lw2[7] = b.w;
    }

    float m = -INFINITY, s = 0.f;
    float acc[8] = {0.f, 0.f, 0.f, 0.f, 0.f, 0.f, 0.f, 0.f};

    for (int n = start + warp; n < end; n += 8) {
        const float4* fr = reinterpret_cast<const float4*>(nf + (size_t)n * F) + lane * 2;
        float4 f0 = fr[0], f1 = fr[1];
        float d = f0.x * lw2[0];
        d = fmaf(f0.y, lw2[1], d);
        d = fmaf(f0.z, lw2[2], d);
        d = fmaf(f0.w, lw2[3], d);
        d = fmaf(f1.x, lw2[4], d);
        d = fmaf(f1.y, lw2[5], d);
        d = fmaf(f1.z, lw2[6], d);
        d = fmaf(f1.w, lw2[7], d);
        #pragma unroll
        for (int o = 16; o; o >>= 1) d += __shfl_xor_sync(0xffffffffu, d, o);

        float t  = c + d;
        float z  = t > 0.f ? t : 0.01f * t;      // leaky_relu 0.01
        float mn = fmaxf(m, z);
        float sc = expf(m - mn);                 // m=-inf first iter -> 0
        float e  = expf(z - mn);
        s = fmaf(s, sc, e);
        acc[0] = fmaf(acc[0], sc, e * f0.x);
        acc[1] = fmaf(acc[1], sc, e * f0.y);
        acc[2] = fmaf(acc[2], sc, e * f0.z);
        acc[3] = fmaf(acc[3], sc, e * f0.w);
        acc[4] = fmaf(acc[4], sc, e * f1.x);
        acc[5] = fmaf(acc[5], sc, e * f1.y);
        acc[6] = fmaf(acc[6], sc, e * f1.z);
        acc[7] = fmaf(acc[7], sc, e * f1.w);
        m = mn;
    }

    if (lane == 0) { s_m[warp] = m; s_s[warp] = s; }
    #pragma unroll
    for (int j = 0; j < 8; ++j) s_acc[warp][lane * 8 + j] = acc[j];
    __syncthreads();

    // merge 8 warp-partials (associative softmax combine); thread t owns dim t
    float M = -INFINITY;
    #pragma unroll
    for (int w = 0; w < 8; ++w) M = fmaxf(M, s_m[w]);
    float S = 0.f, val = 0.f;
    #pragma unroll
    for (int w = 0; w < 8; ++w) {
        float ew = (s_s[w] > 0.f) ? expf(s_m[w] - M) : 0.f;
        S   = fmaf(s_s[w], ew, S);
        val = fmaf(s_acc[w][tid], ew, val);
    }
    g_wf[g * F + tid] = (S > 0.f) ? val / S : 0.f;
    if (tid == 0) g_cnt[g] = end - start;
}

// ---------------- tiled SGEMM: C[M,N] = A[M,K] @ W[N,K]^T + bias ----------------
template <int BM, int BN, int BK, int TM, int TN, int EPI>
__device__ __forceinline__ void gemm_body(
    const float* __restrict__ A, const float* __restrict__ W,
    const float* __restrict__ bias, float* __restrict__ C,
    const int* __restrict__ cnt, int M, int N, int K)
{
    constexpr int TX = BN / TN;
    constexpr int TY = BM / TM;
    constexpr int NT = TX * TY;   // 256

    __shared__ float As[BK][BM + 4];
    __shared__ float Ws[BK][BN + 4];

    const int tid  = threadIdx.x;
    const int tx   = tid % TX;
    const int ty   = tid / TX;
    const int row0 = blockIdx.x * BM;
    const int col0 = blockIdx.y * BN;

    float acc[TM][TN];
    #pragma unroll
    for (int i = 0; i < TM; ++i)
        #pragma unroll
        for (int j = 0; j < TN; ++j) acc[i][j] = 0.f;

    for (int k0 = 0; k0 < K; k0 += BK) {
        constexpr int AV = BM * BK / 4;
        #pragma unroll
        for (int i = 0; i < AV / NT; ++i) {
            int idx = tid + i * NT;
            int r   = idx / (BK / 4);
            int c4  = idx % (BK / 4);
            float4 v = *reinterpret_cast<const float4*>(
                A + (size_t)(row0 + r) * K + k0 + c4 * 4);
            As[c4 * 4 + 0][r] = v.x;
            As[c4 * 4 + 1][r] = v.y;
            As[c4 * 4 + 2][r] = v.z;
            As[c4 * 4 + 3][r] = v.w;
        }
        constexpr int WV = BN * BK / 4;
        #pragma unroll
        for (int i = 0; i < WV / NT; ++i) {
            int idx = tid + i * NT;
            int r   = idx / (BK / 4);
            int c4  = idx % (BK / 4);
            float4 v = *reinterpret_cast<const float4*>(
                W + (size_t)(col0 + r) * K + k0 + c4 * 4);
            Ws[c4 * 4 + 0][r] = v.x;
            Ws[c4 * 4 + 1][r] = v.y;
            Ws[c4 * 4 + 2][r] = v.z;
            Ws[c4 * 4 + 3][r] = v.w;
        }
        __syncthreads();
        #pragma unroll
        for (int kk = 0; kk < BK; ++kk) {
            float ra[TM], rw[TN];
            #pragma unroll
            for (int i = 0; i < TM; ++i) ra[i] = As[kk][ty * TM + i];
            #pragma unroll
            for (int j = 0; j < TN; ++j) rw[j] = Ws[kk][tx * TN + j];
            #pragma unroll
            for (int i = 0; i < TM; ++i)
                #pragma unroll
                for (int j = 0; j < TN; ++j)
                    acc[i][j] = fmaf(ra[i], rw[j], acc[i][j]);
        }
        __syncthreads();
    }

    #pragma unroll
    for (int i = 0; i < TM; ++i) {
        int r = row0 + ty * TM + i;
        #pragma unroll
        for (int j = 0; j < TN; ++j) {
            int col = col0 + tx * TN + j;
            float v = acc[i][j] + bias[col];
            if (EPI == 1) {                    // elu + empty-graph zeroing
                v = v > 0.f ? v : expm1f(v);
                if (cnt[r] == 0) v = 0.f;
            }
            C[(size_t)r * N + col] = v;
        }
    }
}

// proj: x = elu(wf @ proj_w.T + proj_b)
__global__ void __launch_bounds__(256) proj_kernel(
    const float* __restrict__ pw, const float* __restrict__ pb)
{
    gemm_body<64, 32, 32, 4, 2, 1>(g_wf, pw, pb, g_x, g_cnt, NG, F, F);
}

// gates: GI = x @ w_ih.T + b_ih ; GH = h @ w_hh.T + b_hh   (blockIdx.z selects)
__global__ void __launch_bounds__(256) gates_kernel(
    const float* __restrict__ gf,
    const float* __restrict__ wih, const float* __restrict__ whh,
    const float* __restrict__ bih, const float* __restrict__ bhh)
{
    const float* A  = blockIdx.z ? gf  : g_x;
    const float* Wt = blockIdx.z ? whh : wih;
    const float* b  = blockIdx.z ? bhh : bih;
    float*       Cp = blockIdx.z ? g_gh : g_gi;
    gemm_body<128, 64, 16, 8, 4, 0>(A, Wt, b, Cp, nullptr, NG, 3 * F, F);
}

// ---------------- GRU elementwise ----------------
__global__ void __launch_bounds__(256) gru_kernel(
    const float* __restrict__ gf, float* __restrict__ out)
{
    int idx = blockIdx.x * blockDim.x + threadIdx.x;
    if (idx >= NG * F) return;
    int g = idx >> 8;
    int d = idx & (F - 1);
    const float* gi = g_gi + (size_t)g * 3 * F;
    const float* gh = g_gh + (size_t)g * 3 * F;
    float ir = gi[d], iz = gi[F + d], inn = gi[2 * F + d];
    float hr = gh[d], hz = gh[F + d], hn  = gh[2 * F + d];
    float h  = gf[idx];
    float r  = 1.f / (1.f + expf(-(ir + hr)));
    float z  = 1.f / (1.f + expf(-(iz + hz)));
    float n  = tanhf(fmaf(r, hn, inn));
    out[idx] = fmaf(1.f - z, n, z * h);
}

// ---------------- launch ----------------
extern "C" void kernel_launch(void* const* d_in, const int* in_sizes, int n_in,
                              void* d_out, int out_size)
{
    // num_graphs scalar may or may not occupy an input slot
    int o = (n_in >= 12) ? 1 : 0;
    const float* nf  = (const float*)d_in[0];
    const float* gf  = (const float*)d_in[1];
    const int*   seg = (const int*)  d_in[2];
    const float* lw  = (const float*)d_in[3 + o];
    const float* lb  = (const float*)d_in[4 + o];
    const float* pw  = (const float*)d_in[5 + o];
    const float* pb  = (const float*)d_in[6 + o];
    const float* wih = (const float*)d_in[7 + o];
    const float* whh = (const float*)d_in[8 + o];
    const float* bih = (const float*)d_in[9 + o];
    const float* bhh = (const float*)d_in[10 + o];
    float* out = (float*)d_out;
    int n_nodes = in_sizes[0] / F;

    boundary_kernel<<<(n_nodes + 255) / 256, 256>>>(seg, n_nodes);
    pool_kernel<<<NG, 256>>>(nf, gf, lw, lb);
    proj_kernel<<<dim3(NG / 64, F / 32), 256>>>(pw, pb);
    gates_kernel<<<dim3(NG / 128, (3 * F) / 64, 2), 256>>>(gf, wih, whh, bih, bhh);
    gru_kernel<<<(NG * F + 255) / 256, 256>>>(gf, out);
}

// round 2
// speedup vs baseline: 1.0748x; 1.0748x over previous
#include <cuda_runtime.h>
#include <math.h>

#define F   256
#define NG  1024

// ---------------- scratch (no allocation allowed) ----------------
__device__ float g_wf[NG * F];          // softmax-weighted feature mean per graph
__device__ int   g_cnt[NG];             // node count per graph
__device__ int   g_bound[NG + 1];       // segment boundaries
__device__ float g_x[NG * F];           // elu(proj(wf))
__device__ float g_gi[NG * 3 * F];      // x @ w_ih.T + b_ih
__device__ float g_gh[NG * 3 * F];      // h @ w_hh.T + b_hh

// ---------------- segment boundary scan (segment_ids sorted) ----------------
__global__ void boundary_kernel(const int* __restrict__ seg, int n) {
    int i = blockIdx.x * blockDim.x + threadIdx.x;
    if (i >= n) return;
    int s = seg[i];
    if (i == 0) {
        for (int g = 0; g <= s; ++g) g_bound[g] = 0;
    } else {
        int p = seg[i - 1];
        for (int g = p + 1; g <= s; ++g) g_bound[g] = i;
    }
    if (i == n - 1) {
        for (int g = s + 1; g <= NG; ++g) g_bound[g] = n;
    }
}

// ---------------- pooling: one block per graph, online softmax ----------------
// wf[g] = sum_n softmax(z_n) * node_feats[n],   z_n = leaky_relu(c_g + nf_n . lw2 + b)
__global__ void __launch_bounds__(256) pool_kernel(
    const float* __restrict__ nf, const float* __restrict__ gf,
    const float* __restrict__ lw, const float* __restrict__ lb)
{
    const int g    = blockIdx.x;
    const int tid  = threadIdx.x;
    const int warp = tid >> 5;
    const int lane = tid & 31;

    __shared__ float s_red[8];
    __shared__ float s_c;
    __shared__ float s_m[8], s_s[8];
    __shared__ float s_acc[8][F];

    // c_g = relu(g_feats[g]) . lw[0:256] + b
    {
        float v = fmaxf(gf[g * F + tid], 0.f) * lw[tid];
        #pragma unroll
        for (int o = 16; o; o >>= 1) v += __shfl_xor_sync(0xffffffffu, v, o);
        if (lane == 0) s_red[warp] = v;
    }
    __syncthreads();
    if (tid == 0) {
        float c = lb[0];
        #pragma unroll
        for (int w = 0; w < 8; ++w) c += s_red[w];
        s_c = c;
    }
    __syncthreads();
    const float c     = s_c;
    const int   start = g_bound[g];
    const int   end   = g_bound[g + 1];

    // per-lane chunk of logit_w node half: dims lane*8 .. lane*8+7
    float lw2[8];
    {
        const float4* p = reinterpret_cast<const float4*>(lw + F) + lane * 2;
        float4 a = p[0], b = p[1];
        lw2[0] = a.x; lw2[1] = a.y; lw2[2] = a.z; lw2[3] = a.w;
        lw2[4] = b.x; lw2[5] = b.y; lw2[6] = b.z; lw2[7] = b.w;
    }

    float m = -INFINITY, s = 0.f;
    float acc[8] = {0.f, 0.f, 0.f, 0.f, 0.f, 0.f, 0.f, 0.f};

    int n = start + warp;
    // ---- unroll-by-2: nodes n and n+8 with a joint rescale ----
    for (; n + 8 < end; n += 16) {
        const float4* fa = reinterpret_cast<const float4*>(nf + (size_t)n * F) + lane * 2;
        const float4* fb = reinterpret_cast<const float4*>(nf + (size_t)(n + 8) * F) + lane * 2;
        float4 a0 = fa[0], a1 = fa[1];
        float4 b0 = fb[0], b1 = fb[1];

        float d1 = a0.x * lw2[0];
        d1 = fmaf(a0.y, lw2[1], d1); d1 = fmaf(a0.z, lw2[2], d1); d1 = fmaf(a0.w, lw2[3], d1);
        d1 = fmaf(a1.x, lw2[4], d1); d1 = fmaf(a1.y, lw2[5], d1);
        d1 = fmaf(a1.z, lw2[6], d1); d1 = fmaf(a1.w, lw2[7], d1);
        float d2 = b0.x * lw2[0];
        d2 = fmaf(b0.y, lw2[1], d2); d2 = fmaf(b0.z, lw2[2], d2); d2 = fmaf(b0.w, lw2[3], d2);
        d2 = fmaf(b1.x, lw2[4], d2); d2 = fmaf(b1.y, lw2[5], d2);
        d2 = fmaf(b1.z, lw2[6], d2); d2 = fmaf(b1.w, lw2[7], d2);
        #pragma unroll
        for (int o = 16; o; o >>= 1) {
            d1 += __shfl_xor_sync(0xffffffffu, d1, o);
            d2 += __shfl_xor_sync(0xffffffffu, d2, o);
        }
        float t1 = c + d1, t2 = c + d2;
        float z1 = t1 > 0.f ? t1 : 0.01f * t1;
        float z2 = t2 > 0.f ? t2 : 0.01f * t2;
        float mn = fmaxf(m, fmaxf(z1, z2));
        float sc = __expf(m - mn);
        float e1 = __expf(z1 - mn);
        float e2 = __expf(z2 - mn);
        s = fmaf(s, sc, e1 + e2);
        acc[0] = fmaf(acc[0], sc, fmaf(e1, a0.x, e2 * b0.x));
        acc[1] = fmaf(acc[1], sc, fmaf(e1, a0.y, e2 * b0.y));
        acc[2] = fmaf(acc[2], sc, fmaf(e1, a0.z, e2 * b0.z));
        acc[3] = fmaf(acc[3], sc, fmaf(e1, a0.w, e2 * b0.w));
        acc[4] = fmaf(acc[4], sc, fmaf(e1, a1.x, e2 * b1.x));
        acc[5] = fmaf(acc[5], sc, fmaf(e1, a1.y, e2 * b1.y));
        acc[6] = fmaf(acc[6], sc, fmaf(e1, a1.z, e2 * b1.z));
        acc[7] = fmaf(acc[7], sc, fmaf(e1, a1.w, e2 * b1.w));
        m = mn;
    }
    // ---- tail: at most one node left for this warp ----
    if (n < end) {
        const float4* fr = reinterpret_cast<const float4*>(nf + (size_t)n * F) + lane * 2;
        float4 f0 = fr[0], f1 = fr[1];
        float d = f0.x * lw2[0];
        d = fmaf(f0.y, lw2[1], d); d = fmaf(f0.z, lw2[2], d); d = fmaf(f0.w, lw2[3], d);
        d = fmaf(f1.x, lw2[4], d); d = fmaf(f1.y, lw2[5], d);
        d = fmaf(f1.z, lw2[6], d); d = fmaf(f1.w, lw2[7], d);
        #pragma unroll
        for (int o = 16; o; o >>= 1) d += __shfl_xor_sync(0xffffffffu, d, o);
        float t  = c + d;
        float z  = t > 0.f ? t : 0.01f * t;
        float mn = fmaxf(m, z);
        float sc = __expf(m - mn);
        float e  = __expf(z - mn);
        s = fmaf(s, sc, e);
        acc[0] = fmaf(acc[0], sc, e * f0.x);
        acc[1] = fmaf(acc[1], sc, e * f0.y);
        acc[2] = fmaf(acc[2], sc, e * f0.z);
        acc[3] = fmaf(acc[3], sc, e * f0.w);
        acc[4] = fmaf(acc[4], sc, e * f1.x);
        acc[5] = fmaf(acc[5], sc, e * f1.y);
        acc[6] = fmaf(acc[6], sc, e * f1.z);
        acc[7] = fmaf(acc[7], sc, e * f1.w);
        m = mn;
    }

    if (lane == 0) { s_m[warp] = m; s_s[warp] = s; }
    #pragma unroll
    for (int j = 0; j < 8; ++j) s_acc[warp][lane * 8 + j] = acc[j];
    __syncthreads();

    // merge 8 warp-partials; thread t owns dim t
    float M = -INFINITY;
    #pragma unroll
    for (int w = 0; w < 8; ++w) M = fmaxf(M, s_m[w]);
    float S = 0.f, val = 0.f;
    #pragma unroll
    for (int w = 0; w < 8; ++w) {
        float ew = (s_s[w] > 0.f) ? __expf(s_m[w] - M) : 0.f;
        S   = fmaf(s_s[w], ew, S);
        val = fmaf(s_acc[w][tid], ew, val);
    }
    g_wf[g * F + tid] = (S > 0.f) ? val / S : 0.f;
    if (tid == 0) g_cnt[g] = end - start;
}

// ---------------- tiled SGEMM with double-buffered pipeline ----------------
// C[M,N] = A[M,K] @ W[N,K]^T + bias
template <int BM, int BN, int BK, int TM, int TN, int EPI>
__device__ __forceinline__ void gemm_body(
    const float* __restrict__ A, const float* __restrict__ W,
    const float* __restrict__ bias, float* __restrict__ C,
    const int* __restrict__ cnt, int M, int N, int K)
{
    constexpr int TX = BN / TN;
    constexpr int TY = BM / TM;
    constexpr int NT = TX * TY;   // 256
    constexpr int AV = BM * BK / 4 / NT;   // float4 loads/thread for A
    constexpr int WV = BN * BK / 4 / NT;   // float4 loads/thread for W
    static_assert(AV >= 1 && WV >= 1, "tile too small");

    __shared__ float As[2][BK][BM + 4];
    __shared__ float Ws[2][BK][BN + 4];

    const int tid  = threadIdx.x;
    const int tx   = tid % TX;
    const int ty   = tid / TX;
    const int row0 = blockIdx.x * BM;
    const int col0 = blockIdx.y * BN;

    float4 aReg[AV], wReg[WV];

    auto ldgA = [&](int k0) {
        #pragma unroll
        for (int i = 0; i < AV; ++i) {
            int idx = tid + i * NT;
            int r   = idx / (BK / 4);
            int c4  = idx % (BK / 4);
            aReg[i] = *reinterpret_cast<const float4*>(
                A + (size_t)(row0 + r) * K + k0 + c4 * 4);
        }
    };
    auto ldgW = [&](int k0) {
        #pragma unroll
        for (int i = 0; i < WV; ++i) {
            int idx = tid + i * NT;
            int r   = idx / (BK / 4);
            int c4  = idx % (BK / 4);
            wReg[i] = *reinterpret_cast<const float4*>(
                W + (size_t)(col0 + r) * K + k0 + c4 * 4);
        }
    };
    auto sts = [&](int buf) {
        #pragma unroll
        for (int i = 0; i < AV; ++i) {
            int idx = tid + i * NT;
            int r   = idx / (BK / 4);
            int c4  = idx % (BK / 4);
            As[buf][c4 * 4 + 0][r] = aReg[i].x;
            As[buf][c4 * 4 + 1][r] = aReg[i].y;
            As[buf][c4 * 4 + 2][r] = aReg[i].z;
            As[buf][c4 * 4 + 3][r] = aReg[i].w;
        }
        #pragma unroll
        for (int i = 0; i < WV; ++i) {
            int idx = tid + i * NT;
            int r   = idx / (BK / 4);
            int c4  = idx % (BK / 4);
            Ws[buf][c4 * 4 + 0][r] = wReg[i].x;
            Ws[buf][c4 * 4 + 1][r] = wReg[i].y;
            Ws[buf][c4 * 4 + 2][r] = wReg[i].z;
            Ws[buf][c4 * 4 + 3][r] = wReg[i].w;
        }
    };

    float acc[TM][TN];
    #pragma unroll
    for (int i = 0; i < TM; ++i)
        #pragma unroll
        for (int j = 0; j < TN; ++j) acc[i][j] = 0.f;

    const int T = K / BK;
    ldgA(0); ldgW(0);
    sts(0);
    __syncthreads();

    for (int t = 0; t < T; ++t) {
        if (t + 1 < T) { ldgA((t + 1) * BK); ldgW((t + 1) * BK); }
        const int buf = t & 1;
        #pragma unroll
        for (int kk = 0; kk < BK; ++kk) {
            float ra[TM], rw[TN];
            #pragma unroll
            for (int i = 0; i < TM; ++i) ra[i] = As[buf][kk][ty * TM + i];
            #pragma unroll
            for (int j = 0; j < TN; ++j) rw[j] = Ws[buf][kk][tx * TN + j];
            #pragma unroll
            for (int i = 0; i < TM; ++i)
                #pragma unroll
                for (int j = 0; j < TN; ++j)
                    acc[i][j] = fmaf(ra[i], rw[j], acc[i][j]);
        }
        if (t + 1 < T) {
            sts((t + 1) & 1);
            __syncthreads();
        }
    }

    #pragma unroll
    for (int i = 0; i < TM; ++i) {
        int r = row0 + ty * TM + i;
        #pragma unroll
        for (int j = 0; j < TN; ++j) {
            int col = col0 + tx * TN + j;
            float v = acc[i][j] + bias[col];
            if (EPI == 1) {                    // elu + empty-graph zeroing
                v = v > 0.f ? v : expm1f(v);
                if (cnt[r] == 0) v = 0.f;
            }
            C[(size_t)r * N + col] = v;
        }
    }
}

// proj: x = elu(wf @ proj_w.T + proj_b)
__global__ void __launch_bounds__(256) proj_kernel(
    const float* __restrict__ pw, const float* __restrict__ pb)
{
    gemm_body<32, 32, 32, 2, 2, 1>(g_wf, pw, pb, g_x, g_cnt, NG, F, F);
}

// gates: GI = x @ w_ih.T + b_ih ; GH = h @ w_hh.T + b_hh   (blockIdx.z selects)
__global__ void __launch_bounds__(256) gates_kernel(
    const float* __restrict__ gf,
    const float* __restrict__ wih, const float* __restrict__ whh,
    const float* __restrict__ bih, const float* __restrict__ bhh)
{
    const float* A  = blockIdx.z ? gf  : g_x;
    const float* Wt = blockIdx.z ? whh : wih;
    const float* b  = blockIdx.z ? bhh : bih;
    float*       Cp = blockIdx.z ? g_gh : g_gi;
    gemm_body<64, 32, 32, 4, 2, 0>(A, Wt, b, Cp, nullptr, NG, 3 * F, F);
}

// ---------------- GRU elementwise ----------------
__global__ void __launch_bounds__(256) gru_kernel(
    const float* __restrict__ gf, float* __restrict__ out)
{
    int idx = blockIdx.x * blockDim.x + threadIdx.x;
    if (idx >= NG * F) return;
    int g = idx >> 8;
    int d = idx & (F - 1);
    const float* gi = g_gi + (size_t)g * 3 * F;
    const float* gh = g_gh + (size_t)g * 3 * F;
    float ir = gi[d], iz = gi[F + d], inn = gi[2 * F + d];
    float hr = gh[d], hz = gh[F + d], hn  = gh[2 * F + d];
    float h  = gf[idx];
    float r  = 1.f / (1.f + __expf(-(ir + hr)));
    float z  = 1.f / (1.f + __expf(-(iz + hz)));
    float n  = tanhf(fmaf(r, hn, inn));
    out[idx] = fmaf(1.f - z, n, z * h);
}

// ---------------- launch ----------------
extern "C" void kernel_launch(void* const* d_in, const int* in_sizes, int n_in,
                              void* d_out, int out_size)
{
    int o = (n_in >= 12) ? 1 : 0;
    const float* nf  = (const float*)d_in[0];
    const float* gf  = (const float*)d_in[1];
    const int*   seg = (const int*)  d_in[2];
    const float* lw  = (const float*)d_in[3 + o];
    const float* lb  = (const float*)d_in[4 + o];
    const float* pw  = (const float*)d_in[5 + o];
    const float* pb  = (const float*)d_in[6 + o];
    const float* wih = (const float*)d_in[7 + o];
    const float* whh = (const float*)d_in[8 + o];
    const float* bih = (const float*)d_in[9 + o];
    const float* bhh = (const float*)d_in[10 + o];
    float* out = (float*)d_out;
    int n_nodes = in_sizes[0] / F;

    boundary_kernel<<<(n_nodes + 255) / 256, 256>>>(seg, n_nodes);
    pool_kernel<<<NG, 256>>>(nf, gf, lw, lb);
    proj_kernel<<<dim3(NG / 32, F / 32), 256>>>(pw, pb);
    gates_kernel<<<dim3(NG / 64, (3 * F) / 32, 2), 256>>>(gf, wih, whh, bih, bhh);
    gru_kernel<<<(NG * F + 255) / 256, 256>>>(gf, out);
}

// round 3
// speedup vs baseline: 1.1866x; 1.1040x over previous
#include <cuda_runtime.h>
#include <math.h>
#include <stdint.h>

#define F   256
#define NG  1024

// GEMM tile config (all GEMMs): BM=BN=64, BK=16, TM=TN=4, 256 threads
#define BM 64
#define BN 64
#define BK 16

#define GH_BX 16                  // 1024/64
#define GH_BY 12                  // 768/64
#define GH_BLOCKS (GH_BX * GH_BY) // 192

// ---------------- scratch ----------------
__device__ float g_wf[NG * F];
__device__ int   g_cnt[NG];
__device__ float g_x[NG * F];
__device__ float g_gi[NG * 3 * F];
__device__ float g_gh[NG * 3 * F];

// ---------------- f32x2 packed-math helpers ----------------
__device__ __forceinline__ uint64_t pack2(float x, float y) {
    uint64_t r; asm("mov.b64 %0, {%1, %2};" : "=l"(r) : "f"(x), "f"(y)); return r;
}
__device__ __forceinline__ uint64_t bcast2(float x) {
    uint64_t r; asm("mov.b64 %0, {%1, %1};" : "=l"(r) : "f"(x)); return r;
}
__device__ __forceinline__ void ffma2(uint64_t& d, uint64_t a, uint64_t b) {
    asm("fma.rn.f32x2 %0, %1, %2, %0;" : "+l"(d) : "l"(a), "l"(b));
}
__device__ __forceinline__ float2 unpack2(uint64_t v) {
    float2 f; asm("mov.b64 {%0, %1}, %2;" : "=f"(f.x), "=f"(f.y) : "l"(v)); return f;
}

// ---------------- shared memory layouts ----------------
struct SmemGemm {
    float As[2][BK][BM + 4];
    float Ws[2][BK][BN + 4];
};
struct SmemPool {
    float red[8];
    float c;
    float m[8], s[8];
    int   bnd[2];
    float acc[8][F];
};
union SmemU { SmemGemm g; SmemPool p; };

// ---------------- GEMM body: C[M,N] = A[M,K] @ W[N,K]^T + bias ----------------
// double-buffered smem, float4 LDS, fma.rn.f32x2 inner loop
template <int EPI>
__device__ __forceinline__ void gemm_body(
    SmemGemm& S,
    const float* __restrict__ A, const float* __restrict__ W,
    const float* __restrict__ bias, float* __restrict__ C,
    const int* __restrict__ cnt, int N, int K, int bx, int by)
{
    const int tid  = threadIdx.x;
    const int tx   = tid % (BN / 4);       // 0..15
    const int ty   = tid / (BN / 4);       // 0..15
    const int row0 = bx * BM;
    const int col0 = by * BN;

    float4 aR, wR;
    const int r_ld  = tid / (BK / 4);      // 0..63
    const int c4_ld = tid % (BK / 4);      // 0..3

    auto ldg = [&](int k0) {
        aR = *reinterpret_cast<const float4*>(A + (size_t)(row0 + r_ld) * K + k0 + c4_ld * 4);
        wR = *reinterpret_cast<const float4*>(W + (size_t)(col0 + r_ld) * K + k0 + c4_ld * 4);
    };
    auto sts = [&](int buf) {
        S.As[buf][c4_ld * 4 + 0][r_ld] = aR.x;
        S.As[buf][c4_ld * 4 + 1][r_ld] = aR.y;
        S.As[buf][c4_ld * 4 + 2][r_ld] = aR.z;
        S.As[buf][c4_ld * 4 + 3][r_ld] = aR.w;
        S.Ws[buf][c4_ld * 4 + 0][r_ld] = wR.x;
        S.Ws[buf][c4_ld * 4 + 1][r_ld] = wR.y;
        S.Ws[buf][c4_ld * 4 + 2][r_ld] = wR.z;
        S.Ws[buf][c4_ld * 4 + 3][r_ld] = wR.w;
    };

    uint64_t acc2[4][2];
    #pragma unroll
    for (int i = 0; i < 4; ++i) { acc2[i][0] = 0ull; acc2[i][1] = 0ull; }

    const int T = K / BK;
    ldg(0);
    sts(0);
    __syncthreads();

    for (int t = 0; t < T; ++t) {
        if (t + 1 < T) ldg((t + 1) * BK);
        const int buf = t & 1;
        #pragma unroll
        for (int kk = 0; kk < BK; ++kk) {
            float4 ra = *reinterpret_cast<const float4*>(&S.As[buf][kk][ty * 4]);
            float4 rw = *reinterpret_cast<const float4*>(&S.Ws[buf][kk][tx * 4]);
            uint64_t b01 = pack2(rw.x, rw.y);
            uint64_t b23 = pack2(rw.z, rw.w);
            uint64_t a0 = bcast2(ra.x), a1 = bcast2(ra.y);
            uint64_t a2 = bcast2(ra.z), a3 = bcast2(ra.w);
            ffma2(acc2[0][0], a0, b01); ffma2(acc2[0][1], a0, b23);
            ffma2(acc2[1][0], a1, b01); ffma2(acc2[1][1], a1, b23);
            ffma2(acc2[2][0], a2, b01); ffma2(acc2[2][1], a2, b23);
            ffma2(acc2[3][0], a3, b01); ffma2(acc2[3][1], a3, b23);
        }
        if (t + 1 < T) {
            sts((t + 1) & 1);
            __syncthreads();
        }
    }

    #pragma unroll
    for (int i = 0; i < 4; ++i) {
        int r = row0 + ty * 4 + i;
        int cz = (EPI == 1) ? cnt[r] : 1;
        #pragma unroll
        for (int j = 0; j < 2; ++j) {
            int col = col0 + tx * 4 + j * 2;
            float2 v = unpack2(acc2[i][j]);
            v.x += bias[col];
            v.y += bias[col + 1];
            if (EPI == 1) {
                v.x = v.x > 0.f ? v.x : expm1f(v.x);
                v.y = v.y > 0.f ? v.y : expm1f(v.y);
                if (cz == 0) { v.x = 0.f; v.y = 0.f; }
            }
            *reinterpret_cast<float2*>(C + (size_t)r * N + col) = v;
        }
    }
}

// ---------------- binary search (segment_ids sorted) ----------------
__device__ __forceinline__ int lbound(const int* __restrict__ seg, int n, int key) {
    int lo = 0, hi = n;
    while (lo < hi) {
        int mid = (lo + hi) >> 1;
        if (__ldg(seg + mid) < key) lo = mid + 1; else hi = mid;
    }
    return lo;
}

// ---------------- fused: GH GEMM blocks + pool blocks ----------------
// blocks [0, GH_BLOCKS): GH = g_feats @ w_hh.T + b_hh
// blocks [GH_BLOCKS, GH_BLOCKS+NG): online-softmax pool for graph g
__global__ void __launch_bounds__(256) fused_pool_gh_kernel(
    const float* __restrict__ nf, const float* __restrict__ gf,
    const float* __restrict__ lw, const float* __restrict__ lb,
    const float* __restrict__ whh, const float* __restrict__ bhh,
    const int* __restrict__ seg, int n_nodes)
{
    __shared__ SmemU sm;

    if (blockIdx.x < GH_BLOCKS) {
        int bx = blockIdx.x % GH_BX;
        int by = blockIdx.x / GH_BX;
        gemm_body<0>(sm.g, gf, whh, bhh, g_gh, nullptr, 3 * F, F, bx, by);
        return;
    }

    const int g    = blockIdx.x - GH_BLOCKS;
    const int tid  = threadIdx.x;
    const int warp = tid >> 5;
    const int lane = tid & 31;

    // c_g = relu(g_feats[g]) . lw[0:256] + b   (warp partials)
    {
        float v = fmaxf(gf[g * F + tid], 0.f) * lw[tid];
        #pragma unroll
        for (int o = 16; o; o >>= 1) v += __shfl_xor_sync(0xffffffffu, v, o);
        if (lane == 0) sm.p.red[warp] = v;
    }
    // segment bounds via binary search (warp 0 lane 0 / warp 1 lane 0)
    if (tid == 0)  sm.p.bnd[0] = lbound(seg, n_nodes, g);
    if (tid == 32) sm.p.bnd[1] = lbound(seg, n_nodes, g + 1);
    __syncthreads();
    if (tid == 0) {
        float c = lb[0];
        #pragma unroll
        for (int w = 0; w < 8; ++w) c += sm.p.red[w];
        sm.p.c = c;
    }
    __syncthreads();
    const float c     = sm.p.c;
    const int   start = sm.p.bnd[0];
    const int   end   = sm.p.bnd[1];

    float lw2[8];
    {
        const float4* p = reinterpret_cast<const float4*>(lw + F) + lane * 2;
        float4 a = p[0], b = p[1];
        lw2[0] = a.x; lw2[1] = a.y; lw2[2] = a.z; lw2[3] = a.w;
        lw2[4] = b.x; lw2[5] = b.y; lw2[6] = b.z; lw2[7] = b.w;
    }

    float m = -INFINITY, s = 0.f;
    float acc[8] = {0.f, 0.f, 0.f, 0.f, 0.f, 0.f, 0.f, 0.f};

    int n = start + warp;
    for (; n + 8 < end; n += 16) {
        const float4* fa = reinterpret_cast<const float4*>(nf + (size_t)n * F) + lane * 2;
        const float4* fb = reinterpret_cast<const float4*>(nf + (size_t)(n + 8) * F) + lane * 2;
        float4 a0 = fa[0], a1 = fa[1];
        float4 b0 = fb[0], b1 = fb[1];

        float d1 = a0.x * lw2[0];
        d1 = fmaf(a0.y, lw2[1], d1); d1 = fmaf(a0.z, lw2[2], d1); d1 = fmaf(a0.w, lw2[3], d1);
        d1 = fmaf(a1.x, lw2[4], d1); d1 = fmaf(a1.y, lw2[5], d1);
        d1 = fmaf(a1.z, lw2[6], d1); d1 = fmaf(a1.w, lw2[7], d1);
        float d2 = b0.x * lw2[0];
        d2 = fmaf(b0.y, lw2[1], d2); d2 = fmaf(b0.z, lw2[2], d2); d2 = fmaf(b0.w, lw2[3], d2);
        d2 = fmaf(b1.x, lw2[4], d2); d2 = fmaf(b1.y, lw2[5], d2);
        d2 = fmaf(b1.z, lw2[6], d2); d2 = fmaf(b1.w, lw2[7], d2);
        #pragma unroll
        for (int o = 16; o; o >>= 1) {
            d1 += __shfl_xor_sync(0xffffffffu, d1, o);
            d2 += __shfl_xor_sync(0xffffffffu, d2, o);
        }
        float t1 = c + d1, t2 = c + d2;
        float z1 = t1 > 0.f ? t1 : 0.01f * t1;
        float z2 = t2 > 0.f ? t2 : 0.01f * t2;
        float mn = fmaxf(m, fmaxf(z1, z2));
        float sc = __expf(m - mn);
        float e1 = __expf(z1 - mn);
        float e2 = __expf(z2 - mn);
        s = fmaf(s, sc, e1 + e2);
        acc[0] = fmaf(acc[0], sc, fmaf(e1, a0.x, e2 * b0.x));
        acc[1] = fmaf(acc[1], sc, fmaf(e1, a0.y, e2 * b0.y));
        acc[2] = fmaf(acc[2], sc, fmaf(e1, a0.z, e2 * b0.z));
        acc[3] = fmaf(acc[3], sc, fmaf(e1, a0.w, e2 * b0.w));
        acc[4] = fmaf(acc[4], sc, fmaf(e1, a1.x, e2 * b1.x));
        acc[5] = fmaf(acc[5], sc, fmaf(e1, a1.y, e2 * b1.y));
        acc[6] = fmaf(acc[6], sc, fmaf(e1, a1.z, e2 * b1.z));
        acc[7] = fmaf(acc[7], sc, fmaf(e1, a1.w, e2 * b1.w));
        m = mn;
    }
    if (n < end) {
        const float4* fr = reinterpret_cast<const float4*>(nf + (size_t)n * F) + lane * 2;
        float4 f0 = fr[0], f1 = fr[1];
        float d = f0.x * lw2[0];
        d = fmaf(f0.y, lw2[1], d); d = fmaf(f0.z, lw2[2], d); d = fmaf(f0.w, lw2[3], d);
        d = fmaf(f1.x, lw2[4], d); d = fmaf(f1.y, lw2[5], d);
        d = fmaf(f1.z, lw2[6], d); d = fmaf(f1.w, lw2[7], d);
        #pragma unroll
        for (int o = 16; o; o >>= 1) d += __shfl_xor_sync(0xffffffffu, d, o);
        float t  = c + d;
        float z  = t > 0.f ? t : 0.01f * t;
        float mn = fmaxf(m, z);
        float sc = __expf(m - mn);
        float e  = __expf(z - mn);
        s = fmaf(s, sc, e);
        acc[0] = fmaf(acc[0], sc, e * f0.x);
        acc[1] = fmaf(acc[1], sc, e * f0.y);
        acc[2] = fmaf(acc[2], sc, e * f0.z);
        acc[3] = fmaf(acc[3], sc, e * f0.w);
        acc[4] = fmaf(acc[4], sc, e * f1.x);
        acc[5] = fmaf(acc[5], sc, e * f1.y);
        acc[6] = fmaf(acc[6], sc, e * f1.z);
        acc[7] = fmaf(acc[7], sc, e * f1.w);
        m = mn;
    }

    if (lane == 0) { sm.p.m[warp] = m; sm.p.s[warp] = s; }
    #pragma unroll
    for (int j = 0; j < 8; ++j) sm.p.acc[warp][lane * 8 + j] = acc[j];
    __syncthreads();

    float M = -INFINITY;
    #pragma unroll
    for (int w = 0; w < 8; ++w) M = fmaxf(M, sm.p.m[w]);
    float S = 0.f, val = 0.f;
    #pragma unroll
    for (int w = 0; w < 8; ++w) {
        float ew = (sm.p.s[w] > 0.f) ? __expf(sm.p.m[w] - M) : 0.f;
        S   = fmaf(sm.p.s[w], ew, S);
        val = fmaf(sm.p.acc[w][tid], ew, val);
    }
    g_wf[g * F + tid] = (S > 0.f) ? val / S : 0.f;
    if (tid == 0) g_cnt[g] = end - start;
}

// proj: x = elu(wf @ proj_w.T + proj_b), zeroed for empty graphs
__global__ void __launch_bounds__(256) proj_kernel(
    const float* __restrict__ pw, const float* __restrict__ pb)
{
    __shared__ SmemGemm sg;
    gemm_body<1>(sg, g_wf, pw, pb, g_x, g_cnt, F, F, blockIdx.x, blockIdx.y);
}

// GI = x @ w_ih.T + b_ih
__global__ void __launch_bounds__(256) gi_kernel(
    const float* __restrict__ wih, const float* __restrict__ bih)
{
    __shared__ SmemGemm sg;
    gemm_body<0>(sg, g_x, wih, bih, g_gi, nullptr, 3 * F, F, blockIdx.x, blockIdx.y);
}

// ---------------- GRU elementwise ----------------
__global__ void __launch_bounds__(256) gru_kernel(
    const float* __restrict__ gf, float* __restrict__ out)
{
    int idx = blockIdx.x * blockDim.x + threadIdx.x;
    if (idx >= NG * F) return;
    int g = idx >> 8;
    int d = idx & (F - 1);
    const float* gi = g_gi + (size_t)g * 3 * F;
    const float* gh = g_gh + (size_t)g * 3 * F;
    float ir = gi[d], iz = gi[F + d], inn = gi[2 * F + d];
    float hr = gh[d], hz = gh[F + d], hn  = gh[2 * F + d];
    float h  = gf[idx];
    float r  = 1.f / (1.f + __expf(-(ir + hr)));
    float z  = 1.f / (1.f + __expf(-(iz + hz)));
    float n  = tanhf(fmaf(r, hn, inn));
    out[idx] = fmaf(1.f - z, n, z * h);
}

// ---------------- launch ----------------
extern "C" void kernel_launch(void* const* d_in, const int* in_sizes, int n_in,
                              void* d_out, int out_size)
{
    int o = (n_in >= 12) ? 1 : 0;
    const float* nf  = (const float*)d_in[0];
    const float* gf  = (const float*)d_in[1];
    const int*   seg = (const int*)  d_in[2];
    const float* lw  = (const float*)d_in[3 + o];
    const float* lb  = (const float*)d_in[4 + o];
    const float* pw  = (const float*)d_in[5 + o];
    const float* pb  = (const float*)d_in[6 + o];
    const float* wih = (const float*)d_in[7 + o];
    const float* whh = (const float*)d_in[8 + o];
    const float* bih = (const float*)d_in[9 + o];
    const float* bhh = (const float*)d_in[10 + o];
    float* out = (float*)d_out;
    int n_nodes = in_sizes[0] / F;

    fused_pool_gh_kernel<<<GH_BLOCKS + NG, 256>>>(nf, gf, lw, lb, whh, bhh, seg, n_nodes);
    proj_kernel<<<dim3(NG / BM, F / BN), 256>>>(pw, pb);
    gi_kernel<<<dim3(NG / BM, (3 * F) / BN), 256>>>(wih, bih);
    gru_kernel<<<(NG * F + 255) / 256, 256>>>(gf, out);
}